// round 17
// baseline (speedup 1.0000x reference)
// R17: R16 base + (1) top-3 fused into sim epilogue (S matrix eliminated; compact
// per-block candidate buffers), (2) kmlp2 fused into mlp1 epilogue via block-reduced
// atomics (g_h eliminated). GEMM core unchanged (pinned ~340 TF/s limb-work).
// Prediction: 2265 -> ~2120-2180 us, rel_err ~1.6e-5.
#include <cuda_runtime.h>
#include <cuda_bf16.h>
#include <math.h>
#include <float.h>
#include <stdint.h>

#define BSZ 8192
#define FDIM 2048
#define DDIM 1024
#define HDIM 3072
#define NBMAX 64   // max N-blocks per sim row (8192/128)

typedef __nv_bfloat16 bf16;
typedef __nv_bfloat162 bf162;

__device__ __align__(16) bf16 g_Pjh[(size_t)3 * BSZ * DDIM];
__device__ __align__(16) bf16 g_Pjl[(size_t)3 * BSZ * DDIM];
__device__ __align__(16) bf16 g_Xh[(size_t)3 * BSZ * FDIM];
__device__ __align__(16) bf16 g_Xl[(size_t)3 * BSZ * FDIM];
__device__ __align__(16) bf16 g_Wth[(size_t)3 * DDIM * FDIM];
__device__ __align__(16) bf16 g_Wtl[(size_t)3 * DDIM * FDIM];
__device__ __align__(16) bf16 g_W1th[(size_t)DDIM * HDIM];
__device__ __align__(16) bf16 g_W1tl[(size_t)DDIM * HDIM];
__device__ float g_cv[3][BSZ][NBMAX * 3];   // per-block top-3 candidate values
__device__ int   g_ci[3][BSZ][NBMAX * 3];   // per-block top-3 candidate col indices
__device__ float g_nrm[3][BSZ];
__device__ int   g_glist[3][BSZ];
__device__ int   g_qidx[3][BSZ];
__device__ int   g_qrow[3][BSZ];
__device__ int   g_cidx[3][BSZ];
__device__ int   g_crow[3][BSZ];
__device__ int   g_cnt[3][4];

__device__ __forceinline__ uint32_t smem_u32(const void* p) {
    uint32_t a;
    asm("{ .reg .u64 t; cvta.to.shared.u64 t, %1; cvt.u32.u64 %0, t; }" : "=r"(a) : "l"(p));
    return a;
}
__device__ __forceinline__ void cpa16(uint32_t dst, const void* src) {
    asm volatile("cp.async.cg.shared.global [%0], [%1], 16;" :: "r"(dst), "l"(src));
}
#define CP_COMMIT() asm volatile("cp.async.commit_group;" ::: "memory")
#define CP_WAIT1()  asm volatile("cp.async.wait_group 1;" ::: "memory")
#define CP_WAIT0()  asm volatile("cp.async.wait_group 0;" ::: "memory")
__device__ __forceinline__ void ldsm4(uint32_t* r, uint32_t addr) {
    asm volatile("ldmatrix.sync.aligned.m8n8.x4.shared.b16 {%0,%1,%2,%3}, [%4];"
                 : "=r"(r[0]), "=r"(r[1]), "=r"(r[2]), "=r"(r[3]) : "r"(addr));
}
__device__ __forceinline__ void mma16(float* d, const uint32_t* a, uint32_t b0, uint32_t b1) {
    asm("mma.sync.aligned.m16n8k16.row.col.f32.bf16.bf16.f32 "
        "{%0,%1,%2,%3}, {%4,%5,%6,%7}, {%8,%9}, {%0,%1,%2,%3};"
        : "+f"(d[0]), "+f"(d[1]), "+f"(d[2]), "+f"(d[3])
        : "r"(a[0]), "r"(a[1]), "r"(a[2]), "r"(a[3]), "r"(b0), "r"(b1));
}
__device__ __forceinline__ bf162 splitlo2(float x, float y, bf162 h) {
    return bf162(__float2bfloat16_rn(x - __bfloat162float(h.x)),
                 __float2bfloat16_rn(y - __bfloat162float(h.y)));
}
__device__ __forceinline__ void recon4(uint2 hh, uint2 ll, float* o) {
    bf162 h0 = *reinterpret_cast<bf162*>(&hh.x), h1 = *reinterpret_cast<bf162*>(&hh.y);
    bf162 l0 = *reinterpret_cast<bf162*>(&ll.x), l1 = *reinterpret_cast<bf162*>(&ll.y);
    o[0] = __bfloat162float(h0.x) + __bfloat162float(l0.x);
    o[1] = __bfloat162float(h0.y) + __bfloat162float(l0.y);
    o[2] = __bfloat162float(h1.x) + __bfloat162float(l1.x);
    o[3] = __bfloat162float(h1.y) + __bfloat162float(l1.y);
}
__device__ __forceinline__ uint32_t gran(int row, int ch) {
    return (uint32_t)((row * 2 + (ch ^ ((row >> 2) & 1))) * 16);
}
// top-3 insert with (value, smaller-index) tiebreak -- order-independent
__device__ __forceinline__ void top3ins(float v, int c,
    float& b0, float& b1, float& b2, int& j0, int& j1, int& j2)
{
    if ((v > b2) || (v == b2 && c < j2)) {
        if ((v > b1) || (v == b1 && c < j1)) {
            if ((v > b0) || (v == b0 && c < j0)) {
                b2 = b1; j2 = j1; b1 = b0; j1 = j0; b0 = v; j0 = c;
            } else { b2 = b1; j2 = j1; b1 = v; j1 = c; }
        } else     { b2 = v; j2 = c; }
    }
}

// GEMM core: CTA 128x128, 8 warps (warp 64x32), k-chunk 16, 3-stage cp.async,
// one __syncthreads per chunk, ldmatrix frags, 3-term bf16 limb emulation.
__device__ __forceinline__ void gemm_core(
    const char* aHi, const char* aLo, size_t aRowOff, int mlp1A,
    const char* bHi, const char* bLo,
    int K, float acc[4][4][4], uint32_t sm0)
{
    const int tid = threadIdx.x, lane = tid & 31, wid = tid >> 5;
    const int wr = wid & 1, wc = wid >> 1;
    const int sr = tid >> 1, sc = tid & 1;
    const uint32_t gOff = gran(sr, sc);
    const uint32_t cB = (uint32_t)sc * 16;
    const int sub = lane >> 3, rl = lane & 7;
    const int lch = sub >> 1, lr8 = (sub & 1) * 8;
    uint32_t ag[4], bg[2];
    #pragma unroll
    for (int i = 0; i < 4; i++) ag[i] = gran(wr * 64 + i * 16 + lr8 + rl, lch);
    #pragma unroll
    for (int g = 0; g < 2; g++) bg[g] = gran(wc * 32 + g * 16 + lr8 + rl, lch);

    const int nch = K / 16;
    auto issue = [&](int ic, uint32_t st) {
        const int kc = ic * 16;
        const char *pa0, *pa1;
        if (!mlp1A) {
            pa0 = aHi + (size_t)kc * 2 + cB;
            pa1 = aLo + (size_t)kc * 2 + cB;
        } else {
            const size_t off = ((size_t)(kc >> 10) * BSZ * DDIM + (size_t)(kc & 1023)) * 2
                             + aRowOff + cB;
            pa0 = aHi + off;
            pa1 = aLo + off;
        }
        cpa16(sm0 + st + gOff, pa0);
        cpa16(sm0 + st + 4096 + gOff, pa1);
        cpa16(sm0 + st + 8192 + gOff, bHi + (size_t)kc * 2 + cB);
        cpa16(sm0 + st + 12288 + gOff, bLo + (size_t)kc * 2 + cB);
        CP_COMMIT();
    };

    issue(0, 0);
    issue(1, 16384);
    int sCur = 0, sNxt = 2;
    for (int ic = 0; ic < nch; ic++) {
        const uint32_t st = (uint32_t)sCur * 16384;
        CP_WAIT1();
        __syncthreads();
        if (ic + 2 < nch) issue(ic + 2, (uint32_t)sNxt * 16384);
        uint32_t A[4][4], B[2][4];
        ldsm4(B[0], sm0 + st + 12288 + bg[0]);
        ldsm4(B[1], sm0 + st + 12288 + bg[1]);
        #pragma unroll
        for (int i = 0; i < 4; i++) ldsm4(A[i], sm0 + st + ag[i]);
        #pragma unroll
        for (int i = 0; i < 4; i++)
            #pragma unroll
            for (int j = 0; j < 4; j++)
                mma16(acc[i][j], A[i], B[j >> 1][j & 1], B[j >> 1][(j & 1) + 2]);
        ldsm4(B[0], sm0 + st + 8192 + bg[0]);
        ldsm4(B[1], sm0 + st + 8192 + bg[1]);
        #pragma unroll
        for (int i = 0; i < 4; i++)
            #pragma unroll
            for (int j = 0; j < 4; j++)
                mma16(acc[i][j], A[i], B[j >> 1][j & 1], B[j >> 1][(j & 1) + 2]);
        #pragma unroll
        for (int i = 0; i < 4; i++) ldsm4(A[i], sm0 + st + 4096 + ag[i]);
        #pragma unroll
        for (int i = 0; i < 4; i++)
            #pragma unroll
            for (int j = 0; j < 4; j++)
                mma16(acc[i][j], A[i], B[j >> 1][j & 1], B[j >> 1][(j & 1) + 2]);
        if (++sCur == 3) sCur = 0;
        if (++sNxt == 3) sNxt = 0;
    }
    CP_WAIT0();   // drain trailing prefetches before epilogues reuse smem
}

// proj GEMMs, all 3 modalities in one launch (blockIdx.z = modality)
__global__ void __launch_bounds__(256, 2) tgemm_proj(
    const float* __restrict__ b0, const float* __restrict__ b1m,
    const float* __restrict__ b2m)
{
    __shared__ __align__(16) char smraw[49152];
    const uint32_t sm0 = smem_u32(smraw);
    const int mode = blockIdx.z;
    const float* bias = (mode == 0) ? b0 : ((mode == 1) ? b1m : b2m);
    const int m0 = blockIdx.y * 128, n0 = blockIdx.x * 128;
    const int sr = threadIdx.x >> 1;

    const size_t xs = (size_t)mode * BSZ * FDIM + (size_t)(m0 + sr) * FDIM;
    const size_t ws = (size_t)mode * DDIM * FDIM + (size_t)(n0 + sr) * FDIM;
    float acc[4][4][4] = {};
    gemm_core((const char*)(g_Xh + xs), (const char*)(g_Xl + xs), 0, 0,
              (const char*)(g_Wth + ws), (const char*)(g_Wtl + ws), FDIM, acc, sm0);

    const int lane = threadIdx.x & 31, wid = threadIdx.x >> 5;
    const int wr = wid & 1, wc = wid >> 1;
    bf16* ph = g_Pjh + (size_t)mode * BSZ * DDIM;
    bf16* pl = g_Pjl + (size_t)mode * BSZ * DDIM;
    #pragma unroll
    for (int i = 0; i < 4; i++) {
        const int r0 = m0 + wr * 64 + i * 16 + (lane >> 2);
        #pragma unroll
        for (int j = 0; j < 4; j++) {
            const int c = n0 + wc * 32 + j * 8 + (lane & 3) * 2;
            const float2 bv = *(const float2*)(bias + c);
            float2 o0 = make_float2(acc[i][j][0] + bv.x, acc[i][j][1] + bv.y);
            float2 o1 = make_float2(acc[i][j][2] + bv.x, acc[i][j][3] + bv.y);
            bf162 h0(__float2bfloat16_rn(o0.x), __float2bfloat16_rn(o0.y));
            bf162 h1(__float2bfloat16_rn(o1.x), __float2bfloat16_rn(o1.y));
            *(bf162*)(ph + (size_t)r0 * DDIM + c) = h0;
            *(bf162*)(ph + (size_t)(r0 + 8) * DDIM + c) = h1;
            *(bf162*)(pl + (size_t)r0 * DDIM + c) = splitlo2(o0.x, o0.y, h0);
            *(bf162*)(pl + (size_t)(r0 + 8) * DDIM + c) = splitlo2(o1.x, o1.y, h1);
        }
    }
}

// mlp1 GEMM fused with mlp2: out[r] += sum_c relu(h[r][c]) * W2[c]
__global__ void __launch_bounds__(256, 2) tgemm_mlp1(
    const float* __restrict__ bias, const float* __restrict__ W2,
    float* __restrict__ out)
{
    __shared__ __align__(16) char smraw[49152];
    const uint32_t sm0 = smem_u32(smraw);
    const int m0 = blockIdx.y * 128, n0 = blockIdx.x * 128;
    const int sr = threadIdx.x >> 1;

    const size_t ws = (size_t)(n0 + sr) * HDIM;
    float acc[4][4][4] = {};
    gemm_core((const char*)g_Pjh, (const char*)g_Pjl,
              (size_t)(m0 + sr) * DDIM * 2, 1,
              (const char*)(g_W1th + ws), (const char*)(g_W1tl + ws), HDIM, acc, sm0);

    const int lane = threadIdx.x & 31, wid = threadIdx.x >> 5;
    const int wr = wid & 1, wc = wid >> 1;
    float psum[8];
    #pragma unroll
    for (int e = 0; e < 8; e++) psum[e] = 0.f;
    #pragma unroll
    for (int i = 0; i < 4; i++) {
        #pragma unroll
        for (int j = 0; j < 4; j++) {
            const int c = n0 + wc * 32 + j * 8 + (lane & 3) * 2;
            const float2 bv = *(const float2*)(bias + c);
            const float2 wv = *(const float2*)(W2 + c);
            psum[i * 2]     += fmaxf(acc[i][j][0] + bv.x, 0.f) * wv.x
                             + fmaxf(acc[i][j][1] + bv.y, 0.f) * wv.y;
            psum[i * 2 + 1] += fmaxf(acc[i][j][2] + bv.x, 0.f) * wv.x
                             + fmaxf(acc[i][j][3] + bv.y, 0.f) * wv.y;
        }
    }
    __syncthreads();                       // all GEMM smem reads complete
    float* rowsum = (float*)smraw;         // reuse GEMM smem for per-row reduction
    const int t = threadIdx.x;
    if (t < 128) rowsum[t] = 0.f;
    __syncthreads();
    #pragma unroll
    for (int i = 0; i < 4; i++) {
        const int lr = wr * 64 + i * 16 + (lane >> 2);
        atomicAdd(&rowsum[lr], psum[i * 2]);
        atomicAdd(&rowsum[lr + 8], psum[i * 2 + 1]);
    }
    __syncthreads();
    if (t < 128) atomicAdd(&out[m0 + t], rowsum[t]);
}

// sim GEMM (all modalities): cosine in registers + per-row top-3 into candidates
__global__ void __launch_bounds__(256, 2) tgemm_sim() {
    const int m = blockIdx.z;
    const int M = g_cnt[m][1], N = g_cnt[m][2];
    const int m0 = blockIdx.y * 128, n0 = blockIdx.x * 128;
    if (m0 >= M || n0 >= N) return;
    __shared__ __align__(16) char smraw[49152];
    const uint32_t sm0 = smem_u32(smraw);
    const int tid = threadIdx.x;
    const int sr = tid >> 1;
    const size_t slab = (size_t)m * BSZ * DDIM;

    const int qi = m0 + sr, ci = n0 + sr;
    const size_t ar = slab + ((qi < M) ? (size_t)g_qrow[m][qi] * DDIM : 0);
    const size_t br = slab + ((ci < N) ? (size_t)g_crow[m][ci] * DDIM : 0);

    float acc[4][4][4] = {};
    gemm_core((const char*)(g_Pjh + ar), (const char*)(g_Pjl + ar), 0, 0,
              (const char*)(g_Pjh + br), (const char*)(g_Pjl + br), DDIM, acc, sm0);

    const int lane = tid & 31, wid = tid >> 5;
    const int wr = wid & 1, wc = wid >> 1;
    float csc[8];
    #pragma unroll
    for (int j = 0; j < 4; j++) {
        const int c = n0 + wc * 32 + j * 8 + (lane & 3) * 2;
        csc[j * 2]     = (c < N)     ? __fdiv_rn(1.0f, g_nrm[m][g_cidx[m][c]])     : 0.0f;
        csc[j * 2 + 1] = (c + 1 < N) ? __fdiv_rn(1.0f, g_nrm[m][g_cidx[m][c + 1]]) : 0.0f;
    }
    __syncthreads();                  // all GEMM smem reads complete; reuse smem
    float* sv2 = (float*)smraw;       // [128 rows][48 slots]
    int*   si2 = (int*)(smraw + 24576);
    const int slot = wc * 4 + (lane & 3);    // 0..15 per row
    #pragma unroll
    for (int half = 0; half < 2; half++) {   // r0 rows (half=0) and r0+8 rows (half=1)
        #pragma unroll
        for (int i = 0; i < 4; i++) {
            const int lr = wr * 64 + i * 16 + (lane >> 2) + half * 8;
            const int r = m0 + lr;
            float b0 = -INFINITY, b1 = -INFINITY, b2 = -INFINITY;
            int   j0 = 0x7fffffff, j1 = 0x7fffffff, j2 = 0x7fffffff;
            if (r < M) {
                const float s = __fdiv_rn(1.0f, g_nrm[m][g_qidx[m][r]]);
                #pragma unroll
                for (int j = 0; j < 4; j++) {
                    const int c = n0 + wc * 32 + j * 8 + (lane & 3) * 2;
                    if (c < N)
                        top3ins(acc[i][j][half * 2] * s * csc[j * 2], c,
                                b0, b1, b2, j0, j1, j2);
                    if (c + 1 < N)
                        top3ins(acc[i][j][half * 2 + 1] * s * csc[j * 2 + 1], c + 1,
                                b0, b1, b2, j0, j1, j2);
                }
            }
            sv2[lr * 48 + slot * 3]     = b0; si2[lr * 48 + slot * 3]     = j0;
            sv2[lr * 48 + slot * 3 + 1] = b1; si2[lr * 48 + slot * 3 + 1] = j1;
            sv2[lr * 48 + slot * 3 + 2] = b2; si2[lr * 48 + slot * 3 + 2] = j2;
        }
    }
    __syncthreads();
    if (tid < 128) {
        const int r = m0 + tid;
        float b0 = -INFINITY, b1 = -INFINITY, b2 = -INFINITY;
        int   j0 = 0x7fffffff, j1 = 0x7fffffff, j2 = 0x7fffffff;
        for (int e = 0; e < 48; e++)
            top3ins(sv2[tid * 48 + e], si2[tid * 48 + e], b0, b1, b2, j0, j1, j2);
        const int bn = blockIdx.x;
        g_cv[m][r][bn * 3]     = b0; g_ci[m][r][bn * 3]     = j0;
        g_cv[m][r][bn * 3 + 1] = b1; g_ci[m][r][bn * 3 + 1] = j1;
        g_cv[m][r][bn * 3 + 2] = b2; g_ci[m][r][bn * 3 + 2] = j2;
    }
}

__global__ void __launch_bounds__(256) splitX(
    const float* __restrict__ x0, const float* __restrict__ x1, const float* __restrict__ x2)
{
    const int m = blockIdx.y;
    const float* X = (m == 0) ? x0 : ((m == 1) ? x1 : x2);
    const size_t i = (size_t)blockIdx.x * 256 + threadIdx.x;
    float4 v = ((const float4*)X)[i];
    bf162 h0(__float2bfloat16_rn(v.x), __float2bfloat16_rn(v.y));
    bf162 h1(__float2bfloat16_rn(v.z), __float2bfloat16_rn(v.w));
    bf162 l0 = splitlo2(v.x, v.y, h0);
    bf162 l1 = splitlo2(v.z, v.w, h1);
    bf162* dh = (bf162*)(g_Xh + (size_t)m * BSZ * FDIM) + i * 2;
    bf162* dl = (bf162*)(g_Xl + (size_t)m * BSZ * FDIM) + i * 2;
    dh[0] = h0; dh[1] = h1;
    dl[0] = l0; dl[1] = l1;
}

__global__ void __launch_bounds__(256) transW(
    const float* __restrict__ W, bf16* __restrict__ Th, bf16* __restrict__ Tl, int K)
{
    __shared__ float t[32][33];
    const int n0 = blockIdx.x * 32, k0 = blockIdx.y * 32;
    const int tx = threadIdx.x & 31, ty = threadIdx.x >> 5;
    #pragma unroll
    for (int j = 0; j < 4; j++)
        t[ty + j * 8][tx] = W[(size_t)(k0 + ty + j * 8) * DDIM + n0 + tx];
    __syncthreads();
    #pragma unroll
    for (int j = 0; j < 4; j++) {
        const int row = ty + j * 8;
        const float v = t[tx][row];
        const bf16 h = __float2bfloat16_rn(v);
        Th[(size_t)(n0 + row) * K + k0 + tx] = h;
        Tl[(size_t)(n0 + row) * K + k0 + tx] =
            __float2bfloat16_rn(v - __bfloat162float(h));
    }
}

__global__ void __launch_bounds__(1024) setup_kernel(
    const int* __restrict__ missing, const float* __restrict__ b2,
    float* __restrict__ out)
{
    __shared__ int sh[1024];
    const int t = threadIdx.x;
    const int base = t * 8;
    // init output with b2 bias (mlp1 epilogue accumulates on top)
    const float b2v = b2[0];
    #pragma unroll
    for (int j = 0; j < 8; j++) out[base + j] = b2v;
    for (int m = 0; m < 3; m++) {
        const int tag = m + 1;
        int a[8];
        int cnt = 0;
        #pragma unroll
        for (int j = 0; j < 8; j++) { a[j] = (missing[base + j] != tag) ? 1 : 0; cnt += a[j]; }
        sh[t] = cnt; __syncthreads();
        for (int off = 1; off < 1024; off <<= 1) {
            int v = (t >= off) ? sh[t - off] : 0; __syncthreads();
            sh[t] += v; __syncthreads();
        }
        const int Nb = sh[1023];
        int pos = sh[t] - cnt;
        #pragma unroll
        for (int j = 0; j < 8; j++) if (a[j]) g_glist[m][pos++] = base + j;
        if (t == 0) g_cnt[m][0] = Nb;
        __syncthreads();
        int qf[8]; cnt = 0;
        #pragma unroll
        for (int j = 0; j < 8; j++) {
            qf[j] = ((missing[base + j] == tag) && (base + j < Nb)) ? 1 : 0; cnt += qf[j];
        }
        sh[t] = cnt; __syncthreads();
        for (int off = 1; off < 1024; off <<= 1) {
            int v = (t >= off) ? sh[t - off] : 0; __syncthreads();
            sh[t] += v; __syncthreads();
        }
        const int nq = sh[1023];
        pos = sh[t] - cnt;
        #pragma unroll
        for (int j = 0; j < 8; j++) if (qf[j]) {
            g_qidx[m][pos] = base + j;
            g_qrow[m][pos] = g_glist[m][base + j];
            pos++;
        }
        if (t == 0) g_cnt[m][1] = nq;
        __syncthreads();
        int cf[8]; cnt = 0;
        #pragma unroll
        for (int j = 0; j < 8; j++) { cf[j] = (a[j] && (base + j < Nb)) ? 1 : 0; cnt += cf[j]; }
        sh[t] = cnt; __syncthreads();
        for (int off = 1; off < 1024; off <<= 1) {
            int v = (t >= off) ? sh[t - off] : 0; __syncthreads();
            sh[t] += v; __syncthreads();
        }
        const int nc = sh[1023];
        pos = sh[t] - cnt;
        #pragma unroll
        for (int j = 0; j < 8; j++) if (cf[j]) {
            g_cidx[m][pos] = base + j;
            g_crow[m][pos] = g_glist[m][base + j];
            pos++;
        }
        if (t == 0) g_cnt[m][2] = nc;
        __syncthreads();
    }
}

// fused: per-bank-row L2 norms + zeroing of missing rows with b >= Nb
__global__ void __launch_bounds__(256) knz(const int* __restrict__ missing) {
    const int m = blockIdx.y, i = blockIdx.x;
    const int t = threadIdx.x;
    const int Nb = g_cnt[m][0];
    if (i < Nb) {
        const int row = g_glist[m][i];
        const size_t base = (size_t)m * BSZ * DDIM + (size_t)row * DDIM;
        uint2 hh = ((const uint2*)(g_Pjh + base))[t];
        uint2 ll = ((const uint2*)(g_Pjl + base))[t];
        float v[4];
        recon4(hh, ll, v);
        float s = v[0] * v[0] + v[1] * v[1] + v[2] * v[2] + v[3] * v[3];
        #pragma unroll
        for (int off = 16; off > 0; off >>= 1) s += __shfl_down_sync(0xffffffffu, s, off);
        __shared__ float red[8];
        if ((t & 31) == 0) red[t >> 5] = s;
        __syncthreads();
        if (t == 0) {
            float tot = 0.f;
            #pragma unroll
            for (int w = 0; w < 8; w++) tot += red[w];
            g_nrm[m][i] = fmaxf(__fsqrt_rn(tot), 1e-8f);
        }
    }
    if (missing[i] == m + 1 && i >= Nb) {
        const size_t off = (size_t)m * BSZ * DDIM + (size_t)i * DDIM;
        ((uint2*)(g_Pjh + off))[t] = make_uint2(0u, 0u);
        ((uint2*)(g_Pjl + off))[t] = make_uint2(0u, 0u);
    }
}

// merge per-block candidates (<= 192) + softmax blend + limb fill
__global__ void __launch_bounds__(256) ktopk() {
    const int m = blockIdx.y, q = blockIdx.x;
    const int nq = g_cnt[m][1];
    if (q >= nq) return;
    const int nc = g_cnt[m][2];
    const int t = threadIdx.x;
    const size_t slab = (size_t)m * BSZ * DDIM;
    const int qb = g_qidx[m][q];
    uint2* __restrict__ dsth = (uint2*)(g_Pjh + slab + (size_t)qb * DDIM);
    uint2* __restrict__ dstl = (uint2*)(g_Pjl + slab + (size_t)qb * DDIM);
    if (nc == 0) {
        dsth[t] = make_uint2(0u, 0u);
        dstl[t] = make_uint2(0u, 0u);
        return;
    }
    __shared__ float fw[3];
    __shared__ int   fr[3];
    if (t == 0) {
        const int nbn = (nc + 127) >> 7;
        float b0 = -INFINITY, b1 = -INFINITY, b2 = -INFINITY;
        int   j0 = 0x7fffffff, j1 = 0x7fffffff, j2 = 0x7fffffff;
        const float* cv = g_cv[m][q];
        const int*   ci = g_ci[m][q];
        for (int e = 0; e < nbn * 3; e++)
            top3ins(cv[e], ci[e], b0, b1, b2, j0, j1, j2);
        float w0 = 1.0f;
        float w1 = (b1 == -INFINITY) ? 0.f : expf(b1 - b0);
        float w2 = (b2 == -INFINITY) ? 0.f : expf(b2 - b0);
        float ws = w0 + w1 + w2;
        fw[0] = __fdiv_rn(w0, ws); fw[1] = __fdiv_rn(w1, ws); fw[2] = __fdiv_rn(w2, ws);
        fr[0] = (j0 == 0x7fffffff) ? 0 : g_crow[m][j0];
        fr[1] = (j1 == 0x7fffffff) ? 0 : g_crow[m][j1];
        fr[2] = (j2 == 0x7fffffff) ? 0 : g_crow[m][j2];
    }
    __syncthreads();
    const float w0 = fw[0], w1 = fw[1], w2 = fw[2];
    const bf16* ph = g_Pjh + slab;
    const bf16* pl = g_Pjl + slab;
    float a[4], b[4], c[4];
    recon4(((const uint2*)(ph + (size_t)fr[0] * DDIM))[t],
           ((const uint2*)(pl + (size_t)fr[0] * DDIM))[t], a);
    recon4(((const uint2*)(ph + (size_t)fr[1] * DDIM))[t],
           ((const uint2*)(pl + (size_t)fr[1] * DDIM))[t], b);
    recon4(((const uint2*)(ph + (size_t)fr[2] * DDIM))[t],
           ((const uint2*)(pl + (size_t)fr[2] * DDIM))[t], c);
    float o[4];
    #pragma unroll
    for (int e = 0; e < 4; e++) o[e] = w0 * a[e] + w1 * b[e] + w2 * c[e];
    bf162 h0(__float2bfloat16_rn(o[0]), __float2bfloat16_rn(o[1]));
    bf162 h1(__float2bfloat16_rn(o[2]), __float2bfloat16_rn(o[3]));
    bf162 l0 = splitlo2(o[0], o[1], h0);
    bf162 l1 = splitlo2(o[2], o[3], h1);
    uint2 oh, ol;
    oh.x = *reinterpret_cast<uint32_t*>(&h0); oh.y = *reinterpret_cast<uint32_t*>(&h1);
    ol.x = *reinterpret_cast<uint32_t*>(&l0); ol.y = *reinterpret_cast<uint32_t*>(&l1);
    dsth[t] = oh;
    dstl[t] = ol;
}

extern "C" void kernel_launch(void* const* d_in, const int* in_sizes, int n_in,
                              void* d_out, int out_size) {
    const float* x[3]  = { (const float*)d_in[0], (const float*)d_in[1], (const float*)d_in[2] };
    const int* missing = (const int*)d_in[3];
    const float* W[3]  = { (const float*)d_in[4], (const float*)d_in[6], (const float*)d_in[8] };
    const float* bb[3] = { (const float*)d_in[5], (const float*)d_in[7], (const float*)d_in[9] };
    const float* W1 = (const float*)d_in[10];
    const float* b1 = (const float*)d_in[11];
    const float* W2 = (const float*)d_in[12];
    const float* b2 = (const float*)d_in[13];
    float* out = (float*)d_out;

    bf16 *wth, *wtl, *w1th, *w1tl;
    cudaGetSymbolAddress((void**)&wth, g_Wth);
    cudaGetSymbolAddress((void**)&wtl, g_Wtl);
    cudaGetSymbolAddress((void**)&w1th, g_W1th);
    cudaGetSymbolAddress((void**)&w1tl, g_W1tl);

    splitX<<<dim3(BSZ * FDIM / 1024, 3), 256>>>(x[0], x[1], x[2]);
    for (int m = 0; m < 3; m++)
        transW<<<dim3(32, FDIM / 32), 256>>>(W[m],
            wth + (size_t)m * DDIM * FDIM, wtl + (size_t)m * DDIM * FDIM, FDIM);
    transW<<<dim3(32, HDIM / 32), 256>>>(W1, w1th, w1tl, HDIM);
    setup_kernel<<<1, 1024>>>(missing, b2, out);

    tgemm_proj<<<dim3(DDIM / 128, BSZ / 128, 3), 256>>>(bb[0], bb[1], bb[2]);

    knz<<<dim3(BSZ, 3), 256>>>(missing);
    tgemm_sim<<<dim3(64, 64, 3), 256>>>();
    ktopk<<<dim3(BSZ, 3), 256>>>();

    tgemm_mlp1<<<dim3(DDIM / 128, BSZ / 128), 256>>>(b1, W2, out);
}